// round 7
// baseline (speedup 1.0000x reference)
#include <cuda_runtime.h>
#include <cuda_fp16.h>
#include <cstdint>

#define BATCH  4
#define SEQ    2048
#define DMODEL 768
#define NHEAD  12
#define HSZ    64
#define MROWS  (BATCH*SEQ)

// Scratch (alloc-free rule). Half precision everywhere.
__device__ __half g_hX[3][MROWS*DMODEL];     // converted queries/keys/values
__device__ __half g_hW[4][DMODEL*DMODEL];    // converted W_Q/W_K/W_V/W_O
__device__ __half g_Q  [MROWS*DMODEL];
__device__ __half g_K  [MROWS*DMODEL];
__device__ __half g_V  [MROWS*DMODEL];
__device__ __half g_Ctx[MROWS*DMODEL];

__device__ __forceinline__ uint32_t pkh2(float lo, float hi) {
    uint32_t d;
    asm("cvt.rn.f16x2.f32 %0, %1, %2;" : "=r"(d) : "f"(hi), "f"(lo));
    return d;
}
__device__ __forceinline__ float ex2(float x) {
    float r; asm("ex2.approx.ftz.f32 %0, %1;" : "=f"(r) : "f"(x)); return r;
}
__device__ __forceinline__ uint32_t smem_u32(const void* p) {
    uint32_t a;
    asm("{ .reg .u64 t; cvta.to.shared.u64 t, %1; cvt.u32.u64 %0, t; }"
        : "=r"(a) : "l"(p));
    return a;
}

#define MMA_F16(d, a, b0v, b1v)                                                \
    asm volatile("mma.sync.aligned.m16n8k16.row.col.f32.f16.f16.f32 "          \
        "{%0,%1,%2,%3}, {%4,%5,%6,%7}, {%8,%9}, {%0,%1,%2,%3};"                \
        : "+f"((d)[0]), "+f"((d)[1]), "+f"((d)[2]), "+f"((d)[3])               \
        : "r"((a)[0]), "r"((a)[1]), "r"((a)[2]), "r"((a)[3]),                  \
          "r"(b0v), "r"(b1v))

#define LDSM4(r, addr)                                                         \
    asm volatile("ldmatrix.sync.aligned.m8n8.x4.shared.b16 {%0,%1,%2,%3}, [%4];" \
        : "=r"((r)[0]), "=r"((r)[1]), "=r"((r)[2]), "=r"((r)[3]) : "r"(addr))
#define LDSM4T(r, addr)                                                        \
    asm volatile("ldmatrix.sync.aligned.m8n8.x4.trans.shared.b16 {%0,%1,%2,%3}, [%4];" \
        : "=r"((r)[0]), "=r"((r)[1]), "=r"((r)[2]), "=r"((r)[3]) : "r"(addr))

#define CP16(dst, src)                                                         \
    asm volatile("cp.async.cg.shared.global [%0], [%1], 16;" :: "r"(dst), "l"(src))
#define CP_COMMIT() asm volatile("cp.async.commit_group;" ::: "memory")
#define CP_WAIT(n)  asm volatile("cp.async.wait_group %0;" :: "n"(n) : "memory")

// ---------------------------------------------------------------------------
// fp32 -> fp16 conversion, 7 tensors in one launch
// ---------------------------------------------------------------------------
struct Cvt7 { const float* s[7]; __half* d[7]; int n4[7]; };

__global__ __launch_bounds__(256)
void convert_k(Cvt7 c) {
    const int y = blockIdx.y;
    const float4* s = (const float4*)c.s[y];
    uint2* d = (uint2*)c.d[y];
    const int n4 = c.n4[y];
    for (int i = blockIdx.x * 256 + threadIdx.x; i < n4; i += gridDim.x * 256) {
        float4 v = s[i];
        d[i] = make_uint2(pkh2(v.x, v.y), pkh2(v.z, v.w));
    }
}

// ---------------------------------------------------------------------------
// GEMM: Y[M,N] = X[M,K] @ W[N,K]^T + bias  (half in, fp32 accum)
// CTA 128x128, 4 warps 2(M)x2(N), warp tile 64x64, k-chunk 32, 4-stage cp.async.
// ---------------------------------------------------------------------------
#define GS   20
#define GBUF (128 * GS)
#define GEMM_SMEM (4 * 2 * GBUF * 4)    // 81920 B

__device__ __forceinline__ void stY(float* Y, size_t off, float v0, float v1) {
    *(float2*)(Y + off) = make_float2(v0, v1);
}
__device__ __forceinline__ void stY(__half* Y, size_t off, float v0, float v1) {
    *(uint32_t*)(Y + off) = pkh2(v0, v1);
}

template<typename YT>
__device__ __forceinline__ void gemm_body(
    const __half* __restrict__ X, const __half* __restrict__ W,
    const float* __restrict__ bias, YT* __restrict__ Y, int m0, int n0)
{
    extern __shared__ uint32_t dsm[];
    const uint32_t sbase = smem_u32(dsm);
    const int tid = threadIdx.x, lane = tid & 31, wid = tid >> 5;
    const int g = lane >> 2, tg = lane & 3;
    const int wm = (wid & 1) * 64, wn = (wid >> 1) * 64;

    const __half* Xb = X + (size_t)m0 * DMODEL;
    const __half* Wb = W + (size_t)n0 * DMODEL;
    const int r0 = tid >> 2, c0 = tid & 3;   // 16B-chunk mapping (128t)

    float acc[4][8][4] = {};

#define G_ISSUE(kt, s) do {                                                    \
        uint32_t ab = sbase + (s) * 2 * GBUF * 4;                              \
        uint32_t bb = ab + GBUF * 4;                                           \
        _Pragma("unroll")                                                      \
        for (int j = 0; j < 4; j++) {                                          \
            const int r = r0 + j * 32;                                         \
            const uint32_t off = (uint32_t)(r * GS + c0 * 4) << 2;             \
            CP16(ab + off, Xb + (size_t)r * DMODEL + (kt) * 32 + c0 * 8);      \
            CP16(bb + off, Wb + (size_t)r * DMODEL + (kt) * 32 + c0 * 8);      \
        } } while (0)

    G_ISSUE(0, 0); CP_COMMIT();
    G_ISSUE(1, 1); CP_COMMIT();
    G_ISSUE(2, 2); CP_COMMIT();

    const uint32_t aF = (uint32_t)((wm + (lane & 15)) * GS + (lane >> 4) * 4) << 2;
    const uint32_t bF = (uint32_t)((wn + (lane >> 4) * 8 + (lane & 7)) * GS
                                   + ((lane >> 3) & 1) * 4) << 2;

    const int NK = DMODEL / 32;   // 24
    for (int kt = 0; kt < NK; kt++) {
        CP_WAIT(2);
        __syncthreads();
        if (kt + 3 < NK) G_ISSUE(kt + 3, (kt + 3) & 3);
        CP_COMMIT();

        const uint32_t sb2 = sbase + (kt & 3) * 2 * GBUF * 4;
        const uint32_t ao = sb2 + aF;
        const uint32_t bo = sb2 + GBUF * 4 + bF;
#pragma unroll
        for (int k16 = 0; k16 < 2; k16++) {
            uint32_t a4[4][4], b4[4][4];
#pragma unroll
            for (int mt = 0; mt < 4; mt++)
                LDSM4(a4[mt], ao + (uint32_t)((mt * 16 * GS + k16 * 8) << 2));
#pragma unroll
            for (int np = 0; np < 4; np++)
                LDSM4(b4[np], bo + (uint32_t)((np * 16 * GS + k16 * 8) << 2));
#pragma unroll
            for (int mt = 0; mt < 4; mt++)
#pragma unroll
                for (int nt = 0; nt < 8; nt++)
                    MMA_F16(acc[mt][nt], a4[mt],
                            b4[nt >> 1][(nt & 1) * 2], b4[nt >> 1][(nt & 1) * 2 + 1]);
        }
    }
#undef G_ISSUE

#pragma unroll
    for (int mt = 0; mt < 4; mt++) {
        const int row = m0 + wm + mt * 16 + g;
#pragma unroll
        for (int nt = 0; nt < 8; nt++) {
            const int col = n0 + wn + nt * 8 + 2 * tg;
            const float b0v = bias[col], b1v = bias[col + 1];
            stY(Y, (size_t)row * DMODEL + col,       acc[mt][nt][0] + b0v, acc[mt][nt][1] + b1v);
            stY(Y, (size_t)(row + 8) * DMODEL + col, acc[mt][nt][2] + b0v, acc[mt][nt][3] + b1v);
        }
    }
}

__global__ __launch_bounds__(128)
void gemm_qkv(const __half* __restrict__ X0, const __half* __restrict__ X1,
              const __half* __restrict__ X2,
              const __half* __restrict__ W0, const float* __restrict__ b0p,
              const __half* __restrict__ W1, const float* __restrict__ b1p,
              const __half* __restrict__ W2, const float* __restrict__ b2p,
              __half* __restrict__ Q, __half* __restrict__ K, __half* __restrict__ V)
{
    const int m0 = blockIdx.y * 128, n0 = blockIdx.x * 128;
    if (blockIdx.z == 0)      gemm_body(X0, W0, b0p, Q, m0, n0);
    else if (blockIdx.z == 1) gemm_body(X1, W1, b1p, K, m0, n0);
    else                      gemm_body(X2, W2, b2p, V, m0, n0);
}

__global__ __launch_bounds__(128)
void gemm_out(const __half* __restrict__ X, const __half* __restrict__ W,
              const float* __restrict__ bias, float* __restrict__ Y)
{
    gemm_body(X, W, bias, Y, blockIdx.y * 128, blockIdx.x * 128);
}

// ---------------------------------------------------------------------------
// fp16 flash attention. CTA = 128 q rows, 4 warps; each warp owns two 16-row
// slabs (wslab and wslab+64) sharing K/V fragments. 3-stage cp.async.
// ---------------------------------------------------------------------------
#define ASH  36
#define ABUF (64 * ASH)
#define ATTN_SMEM (3 * 2 * ABUF * 4)    // 55296 B

__global__ __launch_bounds__(128)
void attn_mma(const __half* __restrict__ Q, const __half* __restrict__ K,
              const __half* __restrict__ V, __half* __restrict__ O)
{
    extern __shared__ uint32_t dsm[];
    const uint32_t sbase = smem_u32(dsm);

    const int tid = threadIdx.x, wid = tid >> 5, lane = tid & 31;
    const int g = lane >> 2, tg = lane & 3;
    const int bh = blockIdx.y, b = bh / NHEAD, h = bh % NHEAD;
    const int q0 = ((int)gridDim.x - 1 - (int)blockIdx.x) * 128;  // heavy first
    const int wslab = wid * 16;

    const __half* Qg = Q + (size_t)b * SEQ * DMODEL + h * HSZ;
    const __half* Kg = K + (size_t)b * SEQ * DMODEL + h * HSZ;
    const __half* Vg = V + (size_t)b * SEQ * DMODEL + h * HSZ;

    // slab s base rows: q0 + s*64 + wslab + {g, g+8}
    const int rA0 = q0 + wslab + g, rA1 = rA0 + 8;        // slab 0
    const int rB0 = rA0 + 64,       rB1 = rB0 + 8;        // slab 1

    uint32_t qh[2][4][4];
#pragma unroll
    for (int s = 0; s < 2; s++) {
        const __half* Qr0 = Qg + (size_t)(s ? rB0 : rA0) * DMODEL;
        const __half* Qr1 = Qg + (size_t)(s ? rB1 : rA1) * DMODEL;
#pragma unroll
        for (int j = 0; j < 4; j++) {
            const int c = j * 16 + 2 * tg;
            qh[s][j][0] = *(const uint32_t*)(Qr0 + c);
            qh[s][j][1] = *(const uint32_t*)(Qr1 + c);
            qh[s][j][2] = *(const uint32_t*)(Qr0 + c + 8);
            qh[s][j][3] = *(const uint32_t*)(Qr1 + c + 8);
        }
    }

    const int ar0 = tid >> 3, ac0 = tid & 7;   // 16B-chunk mapping (128t)

#define A_ISSUE(kt, st) do {                                                   \
        uint32_t kb = sbase + (st) * 2 * ABUF * 4;                             \
        uint32_t vb = kb + ABUF * 4;                                           \
        _Pragma("unroll")                                                      \
        for (int j = 0; j < 4; j++) {                                          \
            const int r = ar0 + j * 16;                                        \
            const uint32_t off = (uint32_t)(r * ASH + ac0 * 4) << 2;           \
            CP16(kb + off, Kg + (size_t)((kt) + r) * DMODEL + ac0 * 8);        \
            CP16(vb + off, Vg + (size_t)((kt) + r) * DMODEL + ac0 * 8);        \
        } } while (0)

    const uint32_t kF = (uint32_t)(((lane >> 4) * 8 + (lane & 7)) * ASH
                                   + ((lane >> 3) & 1) * 4) << 2;
    const uint32_t vF = (uint32_t)((((lane >> 3) & 1) * 8 + (lane & 7)) * ASH
                                   + (lane >> 4) * 4) << 2;

    float o[2][8][4] = {};
    float mv[2] = {-1e30f, -1e30f}, mv1[2] = {-1e30f, -1e30f};
    float lv[2] = {0.f, 0.f},       lv1[2] = {0.f, 0.f};
    const float qs2 = 0.125f * 1.44269504f;

    const int ntiles = q0 / 64 + 2;
    A_ISSUE(0, 0);  CP_COMMIT();
    A_ISSUE(64, 1); CP_COMMIT();

    for (int t = 0; t < ntiles; t++) {
        const int kt = t * 64;
        CP_WAIT(1);
        __syncthreads();
        if (t + 2 < ntiles) A_ISSUE((t + 2) * 64, (t + 2) % 3);
        CP_COMMIT();

        const bool act0 = kt < q0 + wslab + 16;       // slab0 not fully masked
        const uint32_t sb2 = sbase + (t % 3) * 2 * ABUF * 4;
        const uint32_t ko = sb2 + kF;
        const uint32_t vo = sb2 + ABUF * 4 + vF;

        // S = Q @ K^T for both slabs, K frags shared
        float s0[8][4] = {}, s1[8][4] = {};
#pragma unroll
        for (int j = 0; j < 4; j++) {
            uint32_t kb4[4][4];
#pragma unroll
            for (int np = 0; np < 4; np++)
                LDSM4(kb4[np], ko + (uint32_t)((np * 16 * ASH + j * 8) << 2));
#pragma unroll
            for (int nt = 0; nt < 8; nt++) {
                MMA_F16(s1[nt], qh[1][j],
                        kb4[nt >> 1][(nt & 1) * 2], kb4[nt >> 1][(nt & 1) * 2 + 1]);
                if (act0)
                    MMA_F16(s0[nt], qh[0][j],
                            kb4[nt >> 1][(nt & 1) * 2], kb4[nt >> 1][(nt & 1) * 2 + 1]);
            }
        }

        // causal masks
        if (act0 && kt + 64 > q0 + wslab) {
#pragma unroll
            for (int nt = 0; nt < 8; nt++) {
                const int cl = kt + nt * 8 + 2 * tg;
                if (cl     > rA0) s0[nt][0] = -1e30f;
                if (cl + 1 > rA0) s0[nt][1] = -1e30f;
                if (cl     > rA1) s0[nt][2] = -1e30f;
                if (cl + 1 > rA1) s0[nt][3] = -1e30f;
            }
        }
        if (kt + 64 > q0 + 64 + wslab) {
#pragma unroll
            for (int nt = 0; nt < 8; nt++) {
                const int cl = kt + nt * 8 + 2 * tg;
                if (cl     > rB0) s1[nt][0] = -1e30f;
                if (cl + 1 > rB0) s1[nt][1] = -1e30f;
                if (cl     > rB1) s1[nt][2] = -1e30f;
                if (cl + 1 > rB1) s1[nt][3] = -1e30f;
            }
        }

        // online softmax per slab
#pragma unroll
        for (int s = 0; s < 2; s++) {
            float (*sv)[4] = s ? s1 : s0;
            if (!s && !act0) continue;
            float mx0 = -1e30f, mx1 = -1e30f;
#pragma unroll
            for (int nt = 0; nt < 8; nt++) {
                mx0 = fmaxf(mx0, fmaxf(sv[nt][0], sv[nt][1]));
                mx1 = fmaxf(mx1, fmaxf(sv[nt][2], sv[nt][3]));
            }
            mx0 = fmaxf(mx0, __shfl_xor_sync(0xFFFFFFFFu, mx0, 1));
            mx0 = fmaxf(mx0, __shfl_xor_sync(0xFFFFFFFFu, mx0, 2));
            mx1 = fmaxf(mx1, __shfl_xor_sync(0xFFFFFFFFu, mx1, 1));
            mx1 = fmaxf(mx1, __shfl_xor_sync(0xFFFFFFFFu, mx1, 2));

            const float mn0 = fmaxf(mv[s], mx0), mn1 = fmaxf(mv1[s], mx1);
            const float c0 = ex2((mv[s] - mn0) * qs2), c1 = ex2((mv1[s] - mn1) * qs2);
            lv[s] *= c0; lv1[s] *= c1;
#pragma unroll
            for (int dt = 0; dt < 8; dt++) {
                o[s][dt][0] *= c0; o[s][dt][1] *= c0;
                o[s][dt][2] *= c1; o[s][dt][3] *= c1;
            }
            const float mq0 = mn0 * qs2, mq1 = mn1 * qs2;
            float ls0 = 0.f, ls1 = 0.f;
#pragma unroll
            for (int nt = 0; nt < 8; nt++) {
                sv[nt][0] = ex2(sv[nt][0] * qs2 - mq0);
                sv[nt][1] = ex2(sv[nt][1] * qs2 - mq0);
                sv[nt][2] = ex2(sv[nt][2] * qs2 - mq1);
                sv[nt][3] = ex2(sv[nt][3] * qs2 - mq1);
                ls0 += sv[nt][0] + sv[nt][1];
                ls1 += sv[nt][2] + sv[nt][3];
            }
            ls0 += __shfl_xor_sync(0xFFFFFFFFu, ls0, 1);
            ls0 += __shfl_xor_sync(0xFFFFFFFFu, ls0, 2);
            ls1 += __shfl_xor_sync(0xFFFFFFFFu, ls1, 1);
            ls1 += __shfl_xor_sync(0xFFFFFFFFu, ls1, 2);
            lv[s] += ls0; lv1[s] += ls1;
            mv[s] = mn0; mv1[s] = mn1;
        }

        // O += P @ V, V frags shared between slabs
#pragma unroll
        for (int j = 0; j < 4; j++) {
            uint32_t pa0[4], pa1[4];
            pa1[0] = pkh2(s1[2*j  ][0], s1[2*j  ][1]);
            pa1[1] = pkh2(s1[2*j  ][2], s1[2*j  ][3]);
            pa1[2] = pkh2(s1[2*j+1][0], s1[2*j+1][1]);
            pa1[3] = pkh2(s1[2*j+1][2], s1[2*j+1][3]);
            if (act0) {
                pa0[0] = pkh2(s0[2*j  ][0], s0[2*j  ][1]);
                pa0[1] = pkh2(s0[2*j  ][2], s0[2*j  ][3]);
                pa0[2] = pkh2(s0[2*j+1][0], s0[2*j+1][1]);
                pa0[3] = pkh2(s0[2*j+1][2], s0[2*j+1][3]);
            }
#pragma unroll
            for (int dtp = 0; dtp < 4; dtp++) {
                uint32_t vb4[4];
                LDSM4T(vb4, vo + (uint32_t)((j * 16 * ASH + dtp * 8) << 2));
                MMA_F16(o[1][2*dtp    ], pa1, vb4[0], vb4[1]);
                MMA_F16(o[1][2*dtp + 1], pa1, vb4[2], vb4[3]);
                if (act0) {
                    MMA_F16(o[0][2*dtp    ], pa0, vb4[0], vb4[1]);
                    MMA_F16(o[0][2*dtp + 1], pa0, vb4[2], vb4[3]);
                }
            }
        }
    }
#undef A_ISSUE

    __half* Op = O + (size_t)b * SEQ * DMODEL + h * HSZ;
#pragma unroll
    for (int s = 0; s < 2; s++) {
        const float i0 = 1.f / lv[s], i1 = 1.f / lv1[s];
        const int r0s = s ? rB0 : rA0, r1s = s ? rB1 : rA1;
#pragma unroll
        for (int dt = 0; dt < 8; dt++) {
            const int col = dt * 8 + 2 * tg;
            *(uint32_t*)(Op + (size_t)r0s * DMODEL + col) =
                pkh2(o[s][dt][0] * i0, o[s][dt][1] * i0);
            *(uint32_t*)(Op + (size_t)r1s * DMODEL + col) =
                pkh2(o[s][dt][2] * i1, o[s][dt][3] * i1);
        }
    }
}

// ---------------------------------------------------------------------------
extern "C" void kernel_launch(void* const* d_in, const int* in_sizes, int n_in,
                              void* d_out, int out_size)
{
    const float* queries = (const float*)d_in[0];
    const float* keys    = (const float*)d_in[1];
    const float* values  = (const float*)d_in[2];
    const float* W_Q = (const float*)d_in[3];
    const float* b_Q = (const float*)d_in[4];
    const float* W_K = (const float*)d_in[5];
    const float* b_K = (const float*)d_in[6];
    const float* W_V = (const float*)d_in[7];
    const float* b_V = (const float*)d_in[8];
    const float* W_O = (const float*)d_in[9];
    const float* b_O = (const float*)d_in[10];
    float* out = (float*)d_out;

    __half *hX, *hW, *pQ, *pK, *pV, *pC;
    cudaGetSymbolAddress((void**)&hX, g_hX);
    cudaGetSymbolAddress((void**)&hW, g_hW);
    cudaGetSymbolAddress((void**)&pQ, g_Q);
    cudaGetSymbolAddress((void**)&pK, g_K);
    cudaGetSymbolAddress((void**)&pV, g_V);
    cudaGetSymbolAddress((void**)&pC, g_Ctx);

    __half* hXq = hX;
    __half* hXk = hX + (size_t)MROWS * DMODEL;
    __half* hXv = hX + 2 * (size_t)MROWS * DMODEL;
    __half* hWQ = hW;
    __half* hWK = hW + (size_t)DMODEL * DMODEL;
    __half* hWV = hW + 2 * (size_t)DMODEL * DMODEL;
    __half* hWO = hW + 3 * (size_t)DMODEL * DMODEL;

    Cvt7 c;
    c.s[0] = queries; c.d[0] = hXq; c.n4[0] = MROWS * DMODEL / 4;
    c.s[1] = keys;    c.d[1] = hXk; c.n4[1] = MROWS * DMODEL / 4;
    c.s[2] = values;  c.d[2] = hXv; c.n4[2] = MROWS * DMODEL / 4;
    c.s[3] = W_Q;     c.d[3] = hWQ; c.n4[3] = DMODEL * DMODEL / 4;
    c.s[4] = W_K;     c.d[4] = hWK; c.n4[4] = DMODEL * DMODEL / 4;
    c.s[5] = W_V;     c.d[5] = hWV; c.n4[5] = DMODEL * DMODEL / 4;
    c.s[6] = W_O;     c.d[6] = hWO; c.n4[6] = DMODEL * DMODEL / 4;
    dim3 gc(MROWS * DMODEL / 4 / 256 / 6, 7);
    convert_k<<<gc, 256>>>(c);

    cudaFuncSetAttribute(gemm_qkv, cudaFuncAttributeMaxDynamicSharedMemorySize, GEMM_SMEM);
    cudaFuncSetAttribute(gemm_out, cudaFuncAttributeMaxDynamicSharedMemorySize, GEMM_SMEM);
    cudaFuncSetAttribute(attn_mma, cudaFuncAttributeMaxDynamicSharedMemorySize, ATTN_SMEM);

    dim3 g3(DMODEL / 128, MROWS / 128, 3);   // (6, 64, 3)
    gemm_qkv<<<g3, 128, GEMM_SMEM>>>(hXq, hXk, hXv,
                                     hWQ, b_Q, hWK, b_K, hWV, b_V, pQ, pK, pV);

    dim3 ga(SEQ / 128, BATCH * NHEAD);       // (16, 48)
    attn_mma<<<ga, 128, ATTN_SMEM>>>(pQ, pK, pV, pC);

    dim3 gg(DMODEL / 128, MROWS / 128);      // (6, 64)
    gemm_out<<<gg, 128, GEMM_SMEM>>>(pC, hWO, b_O, out);
}

// round 8
// speedup vs baseline: 1.2183x; 1.2183x over previous
#include <cuda_runtime.h>
#include <cuda_fp16.h>
#include <cstdint>

#define BATCH  4
#define SEQ    2048
#define DMODEL 768
#define NHEAD  12
#define HSZ    64
#define MROWS  (BATCH*SEQ)

// Scratch (alloc-free rule). Half precision everywhere.
__device__ __half g_hX[3][MROWS*DMODEL];     // converted queries/keys/values
__device__ __half g_hW[4][DMODEL*DMODEL];    // converted W_Q/W_K/W_V/W_O
__device__ __half g_Q  [MROWS*DMODEL];
__device__ __half g_K  [MROWS*DMODEL];
__device__ __half g_V  [MROWS*DMODEL];
__device__ __half g_Ctx[MROWS*DMODEL];

__device__ __forceinline__ uint32_t pkh2(float lo, float hi) {
    uint32_t d;
    asm("cvt.rn.f16x2.f32 %0, %1, %2;" : "=r"(d) : "f"(hi), "f"(lo));
    return d;
}
__device__ __forceinline__ float ex2(float x) {
    float r; asm("ex2.approx.ftz.f32 %0, %1;" : "=f"(r) : "f"(x)); return r;
}
__device__ __forceinline__ uint32_t smem_u32(const void* p) {
    uint32_t a;
    asm("{ .reg .u64 t; cvta.to.shared.u64 t, %1; cvt.u32.u64 %0, t; }"
        : "=r"(a) : "l"(p));
    return a;
}

#define MMA_F16(d, a, b0v, b1v)                                                \
    asm volatile("mma.sync.aligned.m16n8k16.row.col.f32.f16.f16.f32 "          \
        "{%0,%1,%2,%3}, {%4,%5,%6,%7}, {%8,%9}, {%0,%1,%2,%3};"                \
        : "+f"((d)[0]), "+f"((d)[1]), "+f"((d)[2]), "+f"((d)[3])               \
        : "r"((a)[0]), "r"((a)[1]), "r"((a)[2]), "r"((a)[3]),                  \
          "r"(b0v), "r"(b1v))

#define LDSM4(r, addr)                                                         \
    asm volatile("ldmatrix.sync.aligned.m8n8.x4.shared.b16 {%0,%1,%2,%3}, [%4];" \
        : "=r"((r)[0]), "=r"((r)[1]), "=r"((r)[2]), "=r"((r)[3]) : "r"(addr))
#define LDSM4T(r, addr)                                                        \
    asm volatile("ldmatrix.sync.aligned.m8n8.x4.trans.shared.b16 {%0,%1,%2,%3}, [%4];" \
        : "=r"((r)[0]), "=r"((r)[1]), "=r"((r)[2]), "=r"((r)[3]) : "r"(addr))

#define CP16(dst, src)                                                         \
    asm volatile("cp.async.cg.shared.global [%0], [%1], 16;" :: "r"(dst), "l"(src))
#define CP_COMMIT() asm volatile("cp.async.commit_group;" ::: "memory")
#define CP_WAIT(n)  asm volatile("cp.async.wait_group %0;" :: "n"(n) : "memory")

// ---------------------------------------------------------------------------
// fp32 -> fp16 conversion, 7 tensors in one launch
// ---------------------------------------------------------------------------
struct Cvt7 { const float* s[7]; __half* d[7]; int n4[7]; };

__global__ __launch_bounds__(256)
void convert_k(Cvt7 c) {
    const int y = blockIdx.y;
    const float4* s = (const float4*)c.s[y];
    uint2* d = (uint2*)c.d[y];
    const int n4 = c.n4[y];
    for (int i = blockIdx.x * 256 + threadIdx.x; i < n4; i += gridDim.x * 256) {
        float4 v = s[i];
        d[i] = make_uint2(pkh2(v.x, v.y), pkh2(v.z, v.w));
    }
}

// ---------------------------------------------------------------------------
// GEMM: Y[M,N] = X[M,K] @ W[N,K]^T + bias  (half in, fp32 accum)
// CTA 128x128, 8 warps 2(M)x4(N), warp 64x32, k-chunk 64 halves, 3-stage
// cp.async pipeline (one barrier per 64-k).
// smem row stride GS=36 words (32 data + 4 pad): conflict-free ldmatrix.
// ---------------------------------------------------------------------------
#define GS   36
#define GBUF (128 * GS)
#define GEMM_SMEM (3 * 2 * GBUF * 4)    // 110592 B

__device__ __forceinline__ void stY(float* Y, size_t off, float v0, float v1) {
    *(float2*)(Y + off) = make_float2(v0, v1);
}
__device__ __forceinline__ void stY(__half* Y, size_t off, float v0, float v1) {
    *(uint32_t*)(Y + off) = pkh2(v0, v1);
}

template<typename YT>
__device__ __forceinline__ void gemm_body(
    const __half* __restrict__ X, const __half* __restrict__ W,
    const float* __restrict__ bias, YT* __restrict__ Y, int m0, int n0)
{
    extern __shared__ uint32_t dsm[];
    const uint32_t sbase = smem_u32(dsm);
    const int tid = threadIdx.x, lane = tid & 31, wid = tid >> 5;
    const int g = lane >> 2, tg = lane & 3;
    const int wm = (wid & 1) * 64, wn = (wid >> 1) * 32;

    const __half* Xb = X + (size_t)m0 * DMODEL;
    const __half* Wb = W + (size_t)n0 * DMODEL;
    const int r0 = tid >> 3, c0 = tid & 7;   // row 0..31, 16B chunk 0..7

    float acc[4][4][4] = {};

#define G_ISSUE(kt, s) do {                                                    \
        uint32_t ab = sbase + (s) * 2 * GBUF * 4;                              \
        uint32_t bb = ab + GBUF * 4;                                           \
        _Pragma("unroll")                                                      \
        for (int j = 0; j < 4; j++) {                                          \
            const int r = r0 + j * 32;                                         \
            const uint32_t off = (uint32_t)(r * GS + c0 * 4) << 2;             \
            CP16(ab + off, Xb + (size_t)r * DMODEL + (kt) * 64 + c0 * 8);      \
            CP16(bb + off, Wb + (size_t)r * DMODEL + (kt) * 64 + c0 * 8);      \
        } } while (0)

    G_ISSUE(0, 0); CP_COMMIT();
    G_ISSUE(1, 1); CP_COMMIT();

    const uint32_t aF = (uint32_t)((wm + (lane & 15)) * GS + (lane >> 4) * 4) << 2;
    const uint32_t bF = (uint32_t)((wn + (lane >> 4) * 8 + (lane & 7)) * GS
                                   + ((lane >> 3) & 1) * 4) << 2;

    const int NK = DMODEL / 64;   // 12
    for (int kt = 0; kt < NK; kt++) {
        CP_WAIT(1);
        __syncthreads();
        if (kt + 2 < NK) { G_ISSUE(kt + 2, (kt + 2) % 3); }
        CP_COMMIT();

        const uint32_t sb2 = sbase + (kt % 3) * 2 * GBUF * 4;
        const uint32_t ao = sb2 + aF;
        const uint32_t bo = sb2 + GBUF * 4 + bF;
#pragma unroll
        for (int k16 = 0; k16 < 4; k16++) {
            uint32_t a4[4][4], b4[2][4];
#pragma unroll
            for (int mt = 0; mt < 4; mt++)
                LDSM4(a4[mt], ao + (uint32_t)((mt * 16 * GS + k16 * 8) << 2));
#pragma unroll
            for (int np = 0; np < 2; np++)
                LDSM4(b4[np], bo + (uint32_t)((np * 16 * GS + k16 * 8) << 2));
#pragma unroll
            for (int mt = 0; mt < 4; mt++)
#pragma unroll
                for (int nt = 0; nt < 4; nt++)
                    MMA_F16(acc[mt][nt], a4[mt],
                            b4[nt >> 1][(nt & 1) * 2], b4[nt >> 1][(nt & 1) * 2 + 1]);
        }
    }
#undef G_ISSUE

#pragma unroll
    for (int mt = 0; mt < 4; mt++) {
        const int row = m0 + wm + mt * 16 + g;
#pragma unroll
        for (int nt = 0; nt < 4; nt++) {
            const int col = n0 + wn + nt * 8 + 2 * tg;
            const float b0v = bias[col], b1v = bias[col + 1];
            stY(Y, (size_t)row * DMODEL + col,       acc[mt][nt][0] + b0v, acc[mt][nt][1] + b1v);
            stY(Y, (size_t)(row + 8) * DMODEL + col, acc[mt][nt][2] + b0v, acc[mt][nt][3] + b1v);
        }
    }
}

__global__ __launch_bounds__(256)
void gemm_qkv(const __half* __restrict__ X0, const __half* __restrict__ X1,
              const __half* __restrict__ X2,
              const __half* __restrict__ W0, const float* __restrict__ b0p,
              const __half* __restrict__ W1, const float* __restrict__ b1p,
              const __half* __restrict__ W2, const float* __restrict__ b2p,
              __half* __restrict__ Q, __half* __restrict__ K, __half* __restrict__ V)
{
    const int m0 = blockIdx.y * 128, n0 = blockIdx.x * 128;
    if (blockIdx.z == 0)      gemm_body(X0, W0, b0p, Q, m0, n0);
    else if (blockIdx.z == 1) gemm_body(X1, W1, b1p, K, m0, n0);
    else                      gemm_body(X2, W2, b2p, V, m0, n0);
}

__global__ __launch_bounds__(256)
void gemm_out(const __half* __restrict__ X, const __half* __restrict__ W,
              const float* __restrict__ bias, float* __restrict__ Y)
{
    gemm_body(X, W, bias, Y, blockIdx.y * 128, blockIdx.x * 128);
}

// ---------------------------------------------------------------------------
// fp16 flash attention (R6-proven config). CTA = 128 q rows, 8 warps x 16.
// 3-stage cp.async K/V tiles (64 rows x 64 halves, stride 36 words).
// V frags via ldmatrix.trans. P stays in registers.
// ---------------------------------------------------------------------------
#define ASH  36
#define ABUF (64 * ASH)
#define ATTN_SMEM (3 * 2 * ABUF * 4)    // 55296 B

__global__ __launch_bounds__(256)
void attn_mma(const __half* __restrict__ Q, const __half* __restrict__ K,
              const __half* __restrict__ V, __half* __restrict__ O)
{
    extern __shared__ uint32_t dsm[];
    const uint32_t sbase = smem_u32(dsm);

    const int tid = threadIdx.x, wid = tid >> 5, lane = tid & 31;
    const int g = lane >> 2, tg = lane & 3;
    const int bh = blockIdx.y, b = bh / NHEAD, h = bh % NHEAD;
    const int q0 = ((int)gridDim.x - 1 - (int)blockIdx.x) * 128;  // heavy first
    const int wslab = wid * 16;

    const __half* Qg = Q + (size_t)b * SEQ * DMODEL + h * HSZ;
    const __half* Kg = K + (size_t)b * SEQ * DMODEL + h * HSZ;
    const __half* Vg = V + (size_t)b * SEQ * DMODEL + h * HSZ;

    const int row0 = q0 + wslab + g;
    const int row1 = row0 + 8;

    uint32_t qh[4][4];
    {
        const __half* Qr0 = Qg + (size_t)row0 * DMODEL;
        const __half* Qr1 = Qg + (size_t)row1 * DMODEL;
#pragma unroll
        for (int j = 0; j < 4; j++) {
            const int c = j * 16 + 2 * tg;
            qh[j][0] = *(const uint32_t*)(Qr0 + c);
            qh[j][1] = *(const uint32_t*)(Qr1 + c);
            qh[j][2] = *(const uint32_t*)(Qr0 + c + 8);
            qh[j][3] = *(const uint32_t*)(Qr1 + c + 8);
        }
    }

    const int ar0 = tid >> 3, ac0 = tid & 7;   // 16B-chunk mapping

#define A_ISSUE(kt, s) do {                                                    \
        uint32_t kb = sbase + (s) * 2 * ABUF * 4;                              \
        uint32_t vb = kb + ABUF * 4;                                           \
        _Pragma("unroll")                                                      \
        for (int j = 0; j < 2; j++) {                                          \
            const int r = ar0 + j * 32;                                        \
            const uint32_t off = (uint32_t)(r * ASH + ac0 * 4) << 2;           \
            CP16(kb + off, Kg + (size_t)((kt) + r) * DMODEL + ac0 * 8);        \
            CP16(vb + off, Vg + (size_t)((kt) + r) * DMODEL + ac0 * 8);        \
        } } while (0)

    const uint32_t kF = (uint32_t)(((lane >> 4) * 8 + (lane & 7)) * ASH
                                   + ((lane >> 3) & 1) * 4) << 2;
    const uint32_t vF = (uint32_t)((((lane >> 3) & 1) * 8 + (lane & 7)) * ASH
                                   + (lane >> 4) * 4) << 2;

    float o[8][4] = {};
    float m0v = -1e30f, m1v = -1e30f, l0 = 0.f, l1 = 0.f;
    const float qs2 = 0.125f * 1.44269504f;

    const int ntiles = q0 / 64 + 2;
    A_ISSUE(0, 0);  CP_COMMIT();
    A_ISSUE(64, 1); CP_COMMIT();

    for (int t = 0; t < ntiles; t++) {
        const int kt = t * 64;
        CP_WAIT(1);
        __syncthreads();
        if (t + 2 < ntiles) A_ISSUE((t + 2) * 64, (t + 2) % 3);
        CP_COMMIT();

        if (kt >= q0 + wslab + 16) continue;   // compute-only skip

        const uint32_t sb2 = sbase + (t % 3) * 2 * ABUF * 4;
        const uint32_t ko = sb2 + kF;
        const uint32_t vo = sb2 + ABUF * 4 + vF;

        // S = Q @ K^T
        float s[8][4] = {};
#pragma unroll
        for (int j = 0; j < 4; j++) {
            uint32_t kb4[4][4];
#pragma unroll
            for (int np = 0; np < 4; np++)
                LDSM4(kb4[np], ko + (uint32_t)((np * 16 * ASH + j * 8) << 2));
#pragma unroll
            for (int nt = 0; nt < 8; nt++)
                MMA_F16(s[nt], qh[j],
                        kb4[nt >> 1][(nt & 1) * 2], kb4[nt >> 1][(nt & 1) * 2 + 1]);
        }

        if (kt + 64 > q0 + wslab) {   // diagonal tile for this warp
#pragma unroll
            for (int nt = 0; nt < 8; nt++) {
                const int cl = kt + nt * 8 + 2 * tg;
                if (cl     > row0) s[nt][0] = -1e30f;
                if (cl + 1 > row0) s[nt][1] = -1e30f;
                if (cl     > row1) s[nt][2] = -1e30f;
                if (cl + 1 > row1) s[nt][3] = -1e30f;
            }
        }

        float mx0 = -1e30f, mx1 = -1e30f;
#pragma unroll
        for (int nt = 0; nt < 8; nt++) {
            mx0 = fmaxf(mx0, fmaxf(s[nt][0], s[nt][1]));
            mx1 = fmaxf(mx1, fmaxf(s[nt][2], s[nt][3]));
        }
        mx0 = fmaxf(mx0, __shfl_xor_sync(0xFFFFFFFFu, mx0, 1));
        mx0 = fmaxf(mx0, __shfl_xor_sync(0xFFFFFFFFu, mx0, 2));
        mx1 = fmaxf(mx1, __shfl_xor_sync(0xFFFFFFFFu, mx1, 1));
        mx1 = fmaxf(mx1, __shfl_xor_sync(0xFFFFFFFFu, mx1, 2));

        const float mn0 = fmaxf(m0v, mx0), mn1 = fmaxf(m1v, mx1);
        const float c0 = ex2((m0v - mn0) * qs2), c1 = ex2((m1v - mn1) * qs2);
        l0 *= c0; l1 *= c1;
#pragma unroll
        for (int dt = 0; dt < 8; dt++) {
            o[dt][0] *= c0; o[dt][1] *= c0;
            o[dt][2] *= c1; o[dt][3] *= c1;
        }

        const float mq0 = mn0 * qs2, mq1 = mn1 * qs2;
        float ls0 = 0.f, ls1 = 0.f;
#pragma unroll
        for (int nt = 0; nt < 8; nt++) {
            s[nt][0] = ex2(s[nt][0] * qs2 - mq0);
            s[nt][1] = ex2(s[nt][1] * qs2 - mq0);
            s[nt][2] = ex2(s[nt][2] * qs2 - mq1);
            s[nt][3] = ex2(s[nt][3] * qs2 - mq1);
            ls0 += s[nt][0] + s[nt][1];
            ls1 += s[nt][2] + s[nt][3];
        }
        ls0 += __shfl_xor_sync(0xFFFFFFFFu, ls0, 1);
        ls0 += __shfl_xor_sync(0xFFFFFFFFu, ls0, 2);
        ls1 += __shfl_xor_sync(0xFFFFFFFFu, ls1, 1);
        ls1 += __shfl_xor_sync(0xFFFFFFFFu, ls1, 2);
        l0 += ls0; l1 += ls1;
        m0v = mn0; m1v = mn1;

        // O += P @ V   (P in registers; V B-frags via ldmatrix.trans)
#pragma unroll
        for (int j = 0; j < 4; j++) {
            uint32_t pa[4];
            pa[0] = pkh2(s[2*j  ][0], s[2*j  ][1]);
            pa[1] = pkh2(s[2*j  ][2], s[2*j  ][3]);
            pa[2] = pkh2(s[2*j+1][0], s[2*j+1][1]);
            pa[3] = pkh2(s[2*j+1][2], s[2*j+1][3]);
#pragma unroll
            for (int dtp = 0; dtp < 4; dtp++) {
                uint32_t vb4[4];
                LDSM4T(vb4, vo + (uint32_t)((j * 16 * ASH + dtp * 8) << 2));
                MMA_F16(o[2*dtp    ], pa, vb4[0], vb4[1]);
                MMA_F16(o[2*dtp + 1], pa, vb4[2], vb4[3]);
            }
        }
    }
#undef A_ISSUE

    const float i0 = 1.f / l0, i1 = 1.f / l1;
    __half* Op = O + (size_t)b * SEQ * DMODEL + h * HSZ;
#pragma unroll
    for (int dt = 0; dt < 8; dt++) {
        const int col = dt * 8 + 2 * tg;
        *(uint32_t*)(Op + (size_t)row0 * DMODEL + col) = pkh2(o[dt][0] * i0, o[dt][1] * i0);
        *(uint32_t*)(Op + (size_t)row1 * DMODEL + col) = pkh2(o[dt][2] * i1, o[dt][3] * i1);
    }
}

// ---------------------------------------------------------------------------
extern "C" void kernel_launch(void* const* d_in, const int* in_sizes, int n_in,
                              void* d_out, int out_size)
{
    const float* queries = (const float*)d_in[0];
    const float* keys    = (const float*)d_in[1];
    const float* values  = (const float*)d_in[2];
    const float* W_Q = (const float*)d_in[3];
    const float* b_Q = (const float*)d_in[4];
    const float* W_K = (const float*)d_in[5];
    const float* b_K = (const float*)d_in[6];
    const float* W_V = (const float*)d_in[7];
    const float* b_V = (const float*)d_in[8];
    const float* W_O = (const float*)d_in[9];
    const float* b_O = (const float*)d_in[10];
    float* out = (float*)d_out;

    __half *hX, *hW, *pQ, *pK, *pV, *pC;
    cudaGetSymbolAddress((void**)&hX, g_hX);
    cudaGetSymbolAddress((void**)&hW, g_hW);
    cudaGetSymbolAddress((void**)&pQ, g_Q);
    cudaGetSymbolAddress((void**)&pK, g_K);
    cudaGetSymbolAddress((void**)&pV, g_V);
    cudaGetSymbolAddress((void**)&pC, g_Ctx);

    __half* hXq = hX;
    __half* hXk = hX + (size_t)MROWS * DMODEL;
    __half* hXv = hX + 2 * (size_t)MROWS * DMODEL;
    __half* hWQ = hW;
    __half* hWK = hW + (size_t)DMODEL * DMODEL;
    __half* hWV = hW + 2 * (size_t)DMODEL * DMODEL;
    __half* hWO = hW + 3 * (size_t)DMODEL * DMODEL;

    Cvt7 c;
    c.s[0] = queries; c.d[0] = hXq; c.n4[0] = MROWS * DMODEL / 4;
    c.s[1] = keys;    c.d[1] = hXk; c.n4[1] = MROWS * DMODEL / 4;
    c.s[2] = values;  c.d[2] = hXv; c.n4[2] = MROWS * DMODEL / 4;
    c.s[3] = W_Q;     c.d[3] = hWQ; c.n4[3] = DMODEL * DMODEL / 4;
    c.s[4] = W_K;     c.d[4] = hWK; c.n4[4] = DMODEL * DMODEL / 4;
    c.s[5] = W_V;     c.d[5] = hWV; c.n4[5] = DMODEL * DMODEL / 4;
    c.s[6] = W_O;     c.d[6] = hWO; c.n4[6] = DMODEL * DMODEL / 4;
    dim3 gc(2048, 7);
    convert_k<<<gc, 256>>>(c);

    cudaFuncSetAttribute(gemm_qkv, cudaFuncAttributeMaxDynamicSharedMemorySize, GEMM_SMEM);
    cudaFuncSetAttribute(gemm_out, cudaFuncAttributeMaxDynamicSharedMemorySize, GEMM_SMEM);
    cudaFuncSetAttribute(attn_mma, cudaFuncAttributeMaxDynamicSharedMemorySize, ATTN_SMEM);

    dim3 g3(DMODEL / 128, MROWS / 128, 3);   // (6, 64, 3)
    gemm_qkv<<<g3, 256, GEMM_SMEM>>>(hXq, hXk, hXv,
                                     hWQ, b_Q, hWK, b_K, hWV, b_V, pQ, pK, pV);

    dim3 ga(SEQ / 128, BATCH * NHEAD);       // (16, 48)
    attn_mma<<<ga, 256, ATTN_SMEM>>>(pQ, pK, pV, pC);

    dim3 gg(DMODEL / 128, MROWS / 128);      // (6, 64)
    gemm_out<<<gg, 256, GEMM_SMEM>>>(pC, hWO, b_O, out);
}